// round 12
// baseline (speedup 1.0000x reference)
#include <cuda_runtime.h>
#include <cuda_bf16.h>

#define B_ 512
#define T_ 512
#define N_ 64

#define L2E 1.4426950408889634f   // log2(e)
#define LN2 0.6931471805599453f   // ln(2)

// ---- packed f32x2 + MUFU helpers (sm_103a) ----
__device__ __forceinline__ void ffma2(unsigned long long &d,
                                      unsigned long long a,
                                      unsigned long long b) {
    asm("fma.rn.f32x2 %0, %1, %2, %0;" : "+l"(d) : "l"(a), "l"(b));
}
__device__ __forceinline__ unsigned long long fadd2(unsigned long long a,
                                                    unsigned long long b) {
    unsigned long long d;
    asm("add.rn.f32x2 %0, %1, %2;" : "=l"(d) : "l"(a), "l"(b));
    return d;
}
__device__ __forceinline__ unsigned long long pack2(float lo, float hi) {
    unsigned long long d;
    asm("mov.b64 %0, {%1, %2};" : "=l"(d) : "f"(lo), "f"(hi));
    return d;
}
__device__ __forceinline__ void unpack2(unsigned long long v, float &lo, float &hi) {
    asm("mov.b64 {%0, %1}, %2;" : "=f"(lo), "=f"(hi) : "l"(v));
}
__device__ __forceinline__ float ex2(float x) {
    float r; asm("ex2.approx.f32 %0, %1;" : "=f"(r) : "f"(x)); return r;
}
__device__ __forceinline__ float lg2(float x) {
    float r; asm("lg2.approx.f32 %0, %1;" : "=f"(r) : "f"(x)); return r;
}
// Exact floor-log2 rescale shift via exponent bit-extract (+6 centering).
__device__ __forceinline__ float expq(float E0) {
    return (float)((int)((__float_as_uint(E0) >> 23) & 0xFF) - 121);
}

// Two-column GEMV for one chain: 16 broadcast LDS.128 + 64 FFMA2.
__device__ __forceinline__ void gemv2(const float* __restrict__ vsrc,
                                      const unsigned long long* __restrict__ ETlo,
                                      const unsigned long long* __restrict__ EThi,
                                      float &sLo, float &sHi) {
    const ulonglong2* ev = reinterpret_cast<const ulonglong2*>(vsrc);
    unsigned long long l0 = 0ull, l1 = 0ull, l2 = 0ull, l3 = 0ull;
    unsigned long long h0 = 0ull, h1 = 0ull, h2 = 0ull, h3 = 0ull;
#pragma unroll
    for (int m = 0; m < 8; m++) {
        const ulonglong2 p = ev[2 * m];
        const ulonglong2 q = ev[2 * m + 1];
        ffma2(l0, p.x, ETlo[4 * m + 0]);
        ffma2(h0, p.x, EThi[4 * m + 0]);
        ffma2(l1, p.y, ETlo[4 * m + 1]);
        ffma2(h1, p.y, EThi[4 * m + 1]);
        ffma2(l2, q.x, ETlo[4 * m + 2]);
        ffma2(h2, q.x, EThi[4 * m + 2]);
        ffma2(l3, q.y, ETlo[4 * m + 3]);
        ffma2(h3, q.y, EThi[4 * m + 3]);
    }
    float a, b;
    unpack2(fadd2(fadd2(l0, l1), fadd2(l2, l3)), a, b);
    sLo = a + b;
    unpack2(fadd2(fadd2(h0, h1), fadd2(h2, h3)), a, b);
    sHi = a + b;
}

// SOLO WARPS, TWO SAME-DIRECTION CHAINS PER WARP, forward-backward split.
// 128 blocks x 128 threads = 512 warps = EXACTLY 1 warp per SMSP (single wave).
// Warp w of block: dir = w&1, pair = w>>1 -> batches 4*bid+2*pair (+1).
// Both chains share the SAME register matrix (64 packed f32x2); their GEMVs
// are independent -> ILP-2 fills the chain's latency bubbles with useful work
// instead of a colliding SMSP-mate. A finished chain predicates off its
// stores/R and idles inside the warp (harmless finite math on frozen smem).
// fb-split exact join, unroll-2, exact power-of-2 rescale (validated r7-r11).
__global__ __launch_bounds__(128) void crf_fb(
    const float* __restrict__ inputs,   // [B, T, N]
    const float* __restrict__ trans,    // [N, N]
    const int*   __restrict__ tags,     // [B, T]
    const int*   __restrict__ lens,     // [B]
    float*       __restrict__ out)      // [B + N*N]
{
    const int bid  = blockIdx.x;
    const int tid  = threadIdx.x;
    const int wid  = tid >> 5;
    const int lane = tid & 31;
    const int dir  = wid & 1;                 // 0 = forward, 1 = backward
    const int pi   = wid >> 1;                // batch pair within block
    const int bA   = 4 * bid + 2 * pi;        // chain-A batch
    const int bB   = bA + 1;                  // chain-B batch

    __shared__ __align__(16) float V[4][2][2][68];   // [warp][chain][buf][vec]
    __shared__ float Rsh[4][2];

    // Passthrough copy of transition_params: 128 blocks x 8 float4 = 4096.
    if (tid < 8) {
        const int idx = bid * 8 + tid;
        reinterpret_cast<float4*>(out + B_)[idx] =
            reinterpret_cast<const float4*>(trans)[idx];
    }

    // Register matrix shared by both chains (depends only on dir, lane):
    //  fwd: ET*[m] = exp2(trans[2m..][col]*L2E) for cols lane, lane+32
    //  bwd: ET*[m] = exp2(trans[col][2m..]*L2E) for rows lane, lane+32
    unsigned long long ETlo[32], EThi[32];
#pragma unroll
    for (int m = 0; m < 32; m++) {
        const int iaL = dir ? (lane * N_ + 2 * m)           : ((2 * m) * N_ + lane);
        const int ibL = dir ? (lane * N_ + 2 * m + 1)       : ((2 * m + 1) * N_ + lane);
        const int iaH = dir ? ((lane + 32) * N_ + 2 * m)     : ((2 * m) * N_ + lane + 32);
        const int ibH = dir ? ((lane + 32) * N_ + 2 * m + 1) : ((2 * m + 1) * N_ + lane + 32);
        ETlo[m] = pack2(ex2(trans[iaL] * L2E), ex2(trans[ibL] * L2E));
        EThi[m] = pack2(ex2(trans[iaH] * L2E), ex2(trans[ibH] * L2E));
    }

    const float* emA = inputs + (size_t)bA * T_ * N_;
    const float* emB = inputs + (size_t)bB * T_ * N_;
    const int lenA = lens[bA], lenB = lens[bB];
    const int LA = (lenA > 1) ? lenA - 1 : 0;
    const int LB = (lenB > 1) ? lenB - 1 : 0;
    const int fsA = LA >> 1, fsB = LB >> 1;
    const int nsA = dir ? (LA - fsA) : fsA;
    const int nsB = dir ? (LB - fsB) : fsB;
    const int neA = dir ? (nsA - 1) : nsA;     // last k with a real emission
    const int neB = dir ? (nsB - 1) : nsB;
    const int stA = dir ? LA : 0;
    const int stB = dir ? LB : 0;
    const int dr  = dir ? -1 : 1;

    float (*VA)[68] = V[wid][0];
    float (*VB)[68] = V[wid][1];

    // Init both chains' vectors (+ accumulated log2 shifts).
    float RA, RB;
    if (dir == 0) {
        const float r0 = __ldg(&emA[0]) * L2E;
        RA = r0;
        VA[0][lane]      = ex2(fmaf(emA[lane],      L2E, -r0));
        VA[0][lane + 32] = ex2(fmaf(emA[lane + 32], L2E, -r0));
    } else if (nsA > 0) {
        const size_t o = (size_t)LA * N_;
        const float r0 = __ldg(&emA[o]) * L2E;
        RA = r0;
        VA[0][lane]      = ex2(fmaf(emA[o + lane],      L2E, -r0));
        VA[0][lane + 32] = ex2(fmaf(emA[o + lane + 32], L2E, -r0));
    } else { RA = 0.0f; VA[0][lane] = 1.0f; VA[0][lane + 32] = 1.0f; }

    if (dir == 0) {
        const float r0 = __ldg(&emB[0]) * L2E;
        RB = r0;
        VB[0][lane]      = ex2(fmaf(emB[lane],      L2E, -r0));
        VB[0][lane + 32] = ex2(fmaf(emB[lane + 32], L2E, -r0));
    } else if (nsB > 0) {
        const size_t o = (size_t)LB * N_;
        const float r0 = __ldg(&emB[o]) * L2E;
        RB = r0;
        VB[0][lane]      = ex2(fmaf(emB[o + lane],      L2E, -r0));
        VB[0][lane + 32] = ex2(fmaf(emB[o + lane + 32], L2E, -r0));
    } else { RB = 0.0f; VB[0][lane] = 1.0f; VB[0][lane + 32] = 1.0f; }

    // Emission prefetch (one unrolled pair ahead) for both chains.
    float aAl = 0.f, aAh = 0.f, aBl = 0.f, aBh = 0.f;
    float bAl = 0.f, bAh = 0.f, bBl = 0.f, bBh = 0.f;
    if (1 <= neA) { const int r = (stA + dr) * N_;     aAl = emA[r + lane]; aAh = emA[r + lane + 32]; }
    if (2 <= neA) { const int r = (stA + 2 * dr) * N_; aBl = emA[r + lane]; aBh = emA[r + lane + 32]; }
    if (1 <= neB) { const int r = (stB + dr) * N_;     bAl = emB[r + lane]; bAh = emB[r + lane + 32]; }
    if (2 <= neB) { const int r = (stB + 2 * dr) * N_; bBl = emB[r + lane]; bBh = emB[r + lane + 32]; }

    __syncwarp();

    const int nsMax = (nsA > nsB) ? nsA : nsB;
    int k = 1;
    for (; k + 1 <= nsMax; k += 2) {
        float naAl = 0.f, naAh = 0.f, naBl = 0.f, naBh = 0.f;
        float nbAl = 0.f, nbAh = 0.f, nbBl = 0.f, nbBh = 0.f;
        if (k + 2 <= neA) { const int r = (stA + dr * (k + 2)) * N_; naAl = emA[r + lane]; naAh = emA[r + lane + 32]; }
        if (k + 3 <= neA) { const int r = (stA + dr * (k + 3)) * N_; naBl = emA[r + lane]; naBh = emA[r + lane + 32]; }
        if (k + 2 <= neB) { const int r = (stB + dr * (k + 2)) * N_; nbAl = emB[r + lane]; nbAh = emB[r + lane + 32]; }
        if (k + 3 <= neB) { const int r = (stB + dr * (k + 3)) * N_; nbBl = emB[r + lane]; nbBh = emB[r + lane + 32]; }

        // ---- step A (rescaled): buf0 -> buf1, both chains ----
        {
            const float qA = expq(VA[0][0]);
            const float qB = expq(VB[0][0]);
            float sAlo, sAhi, sBlo, sBhi;
            gemv2(&VA[0][0], ETlo, EThi, sAlo, sAhi);
            gemv2(&VB[0][0], ETlo, EThi, sBlo, sBhi);
            const float mAl = ex2(fmaf(aAl, L2E, -qA));
            const float mAh = ex2(fmaf(aAh, L2E, -qA));
            const float mBl = ex2(fmaf(bAl, L2E, -qB));
            const float mBh = ex2(fmaf(bAh, L2E, -qB));
            if (k <= nsA) { VA[1][lane] = mAl * sAlo; VA[1][lane + 32] = mAh * sAhi; RA += qA; }
            if (k <= nsB) { VB[1][lane] = mBl * sBlo; VB[1][lane + 32] = mBh * sBhi; RB += qB; }
            __syncwarp();
        }
        // ---- step B (no rescale): buf1 -> buf0, both chains ----
        {
            float sAlo, sAhi, sBlo, sBhi;
            gemv2(&VA[1][0], ETlo, EThi, sAlo, sAhi);
            gemv2(&VB[1][0], ETlo, EThi, sBlo, sBhi);
            const float mAl = ex2(aBl * L2E);
            const float mAh = ex2(aBh * L2E);
            const float mBl = ex2(bBl * L2E);
            const float mBh = ex2(bBh * L2E);
            if (k + 1 <= nsA) { VA[0][lane] = mAl * sAlo; VA[0][lane + 32] = mAh * sAhi; }
            if (k + 1 <= nsB) { VB[0][lane] = mBl * sBlo; VB[0][lane + 32] = mBh * sBhi; }
            __syncwarp();
        }
        aAl = naAl; aAh = naAh; aBl = naBl; aBh = naBh;
        bAl = nbAl; bAh = nbAh; bBl = nbBl; bBh = nbBh;
    }

    // Odd leftover step (k == nsMax, A-type).
    if (k <= nsMax) {
        const float qA = expq(VA[0][0]);
        const float qB = expq(VB[0][0]);
        float sAlo, sAhi, sBlo, sBhi;
        gemv2(&VA[0][0], ETlo, EThi, sAlo, sAhi);
        gemv2(&VB[0][0], ETlo, EThi, sBlo, sBhi);
        const float mAl = ex2(fmaf(aAl, L2E, -qA));
        const float mAh = ex2(fmaf(aAh, L2E, -qA));
        const float mBl = ex2(fmaf(bAl, L2E, -qB));
        const float mBh = ex2(fmaf(bAh, L2E, -qB));
        if (k <= nsA) { VA[1][lane] = mAl * sAlo; VA[1][lane + 32] = mAh * sAhi; RA += qA; }
        if (k <= nsB) { VB[1][lane] = mBl * sBlo; VB[1][lane + 32] = mBh * sBhi; RB += qB; }
        __syncwarp();
    }

    // ---- join: warp i handles batch 4*bid + i ----
    if (lane == 0) { Rsh[wid][0] = RA; Rsh[wid][1] = RB; }
    __syncthreads();

    const int i   = wid;
    const int bb  = 4 * bid + i;
    const int fw  = 2 * (i >> 1);             // warp holding this pair's fwd
    const int bw  = fw + 1;                   // warp holding this pair's bwd
    const int c   = i & 1;                    // chain slot within those warps
    const int lenI = lens[bb];
    const int LI   = (lenI > 1) ? lenI - 1 : 0;
    const int fsI  = LI >> 1;
    const int fpar = fsI & 1;
    const int bpar = (LI - fsI) & 1;

    float dv = V[fw][c][fpar][lane]      * V[bw][c][bpar][lane]
             + V[fw][c][fpar][lane + 32] * V[bw][c][bpar][lane + 32];
#pragma unroll
    for (int off = 16; off; off >>= 1)
        dv += __shfl_xor_sync(0xffffffffu, dv, off);

    // Sequence score for batch bb, strided over this warp's 32 lanes.
    const float* emI = inputs + (size_t)bb * T_ * N_;
    const int* tgI = tags + bb * T_;
    float sc = 0.0f;
    for (int q = lane; q < lenI; q += 32)
        sc += emI[q * N_ + tgI[q]];
    for (int q = lane + 1; q < lenI; q += 32)
        sc += trans[tgI[q - 1] * N_ + tgI[q]];
#pragma unroll
    for (int off = 16; off; off >>= 1)
        sc += __shfl_xor_sync(0xffffffffu, sc, off);

    if (lane == 0) {
        const float logZ = (Rsh[fw][c] + Rsh[bw][c] + lg2(dv)) * LN2;
        out[bb] = sc - logZ;
    }
}

extern "C" void kernel_launch(void* const* d_in, const int* in_sizes, int n_in,
                              void* d_out, int out_size) {
    const float* inputs = (const float*)d_in[0];   // [512, 512, 64] f32
    const float* trans  = (const float*)d_in[1];   // [64, 64] f32
    const int*   tags   = (const int*)d_in[2];     // [512, 512] i32
    const int*   lens   = (const int*)d_in[3];     // [512] i32
    float*       out    = (float*)d_out;           // [512 + 4096] f32

    crf_fb<<<B_ / 4, 128>>>(inputs, trans, tags, lens, out);
}

// round 13
// speedup vs baseline: 1.1895x; 1.1895x over previous
#include <cuda_runtime.h>
#include <cuda_bf16.h>

#define B_ 512
#define T_ 512
#define N_ 64

#define L2E 1.4426950408889634f   // log2(e)
#define LN2 0.6931471805599453f   // ln(2)

// Length-scheduled warp classes (batch ranks sorted by len desc):
//  ranks [0,150)   -> SOLO   warps (1 chain/warp)  : 300 warps
//  ranks [150,260) -> PAIR   warps (2 chains/warp) : 110 warps
//  ranks [260,512) -> TRIPLE warps (3 chains/warp) : 168 warps
#define SOLO_B 150
#define PAIR_B 110
#define W_SOLO 300
#define W_PAIR 110
#define W_TRI  168
#define NBLK   145        // 145 blocks x 4 warps = 580 slots (2 idle), single wave

__device__ int d_order[B_];

// ---- packed f32x2 + MUFU helpers (sm_103a) ----
__device__ __forceinline__ void ffma2(unsigned long long &d,
                                      unsigned long long a,
                                      unsigned long long b) {
    asm("fma.rn.f32x2 %0, %1, %2, %0;" : "+l"(d) : "l"(a), "l"(b));
}
__device__ __forceinline__ unsigned long long fadd2(unsigned long long a,
                                                    unsigned long long b) {
    unsigned long long d;
    asm("add.rn.f32x2 %0, %1, %2;" : "=l"(d) : "l"(a), "l"(b));
    return d;
}
__device__ __forceinline__ unsigned long long pack2(float lo, float hi) {
    unsigned long long d;
    asm("mov.b64 %0, {%1, %2};" : "=l"(d) : "f"(lo), "f"(hi));
    return d;
}
__device__ __forceinline__ void unpack2(unsigned long long v, float &lo, float &hi) {
    asm("mov.b64 {%0, %1}, %2;" : "=f"(lo), "=f"(hi) : "l"(v));
}
__device__ __forceinline__ float ex2(float x) {
    float r; asm("ex2.approx.f32 %0, %1;" : "=f"(r) : "f"(x)); return r;
}
__device__ __forceinline__ float lg2(float x) {
    float r; asm("lg2.approx.f32 %0, %1;" : "=f"(r) : "f"(x)); return r;
}
// Exact floor-log2 rescale shift via exponent bit-extract (+6 centering).
__device__ __forceinline__ float expq(float E0) {
    return (float)((int)((__float_as_uint(E0) >> 23) & 0xFF) - 121);
}

// Rank batches by length desc (ties by index): d_order[rank] = batch.
__global__ void rank_kernel(const int* __restrict__ lens) {
    __shared__ int sl[B_];
    const int t = threadIdx.x;
    sl[t] = lens[t];
    __syncthreads();
    const int lb = sl[t];
    int r = 0;
#pragma unroll 8
    for (int k = 0; k < B_; k++) {
        const int lk = sl[k];
        r += (lk > lb) || (lk == lb && k < t);
    }
    d_order[r] = t;
}

// Two-column GEMV: 16 broadcast LDS.128 + 64 FFMA2.
__device__ __forceinline__ void gemv2(const float* __restrict__ vsrc,
                                      const unsigned long long* __restrict__ ETlo,
                                      const unsigned long long* __restrict__ EThi,
                                      float &sLo, float &sHi) {
    const ulonglong2* ev = reinterpret_cast<const ulonglong2*>(vsrc);
    unsigned long long l0 = 0ull, l1 = 0ull, l2 = 0ull, l3 = 0ull;
    unsigned long long h0 = 0ull, h1 = 0ull, h2 = 0ull, h3 = 0ull;
#pragma unroll
    for (int m = 0; m < 8; m++) {
        const ulonglong2 p = ev[2 * m];
        const ulonglong2 q = ev[2 * m + 1];
        ffma2(l0, p.x, ETlo[4 * m + 0]);
        ffma2(h0, p.x, EThi[4 * m + 0]);
        ffma2(l1, p.y, ETlo[4 * m + 1]);
        ffma2(h1, p.y, EThi[4 * m + 1]);
        ffma2(l2, q.x, ETlo[4 * m + 2]);
        ffma2(h2, q.x, EThi[4 * m + 2]);
        ffma2(l3, q.y, ETlo[4 * m + 3]);
        ffma2(h3, q.y, EThi[4 * m + 3]);
    }
    float a, b;
    unpack2(fadd2(fadd2(l0, l1), fadd2(l2, l3)), a, b);
    sLo = a + b;
    unpack2(fadd2(fadd2(h0, h1), fadd2(h2, h3)), a, b);
    sHi = a + b;
}

// NCH same-direction chains in one warp (shared register matrix).
// Unroll-2, exact power-of-2 rescale on A-steps (validated r7-r12).
template <int NCH>
__device__ __forceinline__ void run_chains(
    const float* __restrict__ inputs, const int* __restrict__ lens,
    const int* bb, int dir, int lane,
    const unsigned long long* __restrict__ ETlo,
    const unsigned long long* __restrict__ EThi,
    float (*V)[2][68], float* Rout)
{
    const float* em[NCH];
    int ns[NCH], ne[NCH], st[NCH];
    float R[NCH];
    const int dr = dir ? -1 : 1;

#pragma unroll
    for (int c = 0; c < NCH; c++) {
        em[c] = inputs + (size_t)bb[c] * T_ * N_;
        const int len = lens[bb[c]];
        const int L = (len > 1) ? len - 1 : 0;
        const int fs = L >> 1;
        ns[c] = dir ? (L - fs) : fs;
        ne[c] = dir ? (ns[c] - 1) : ns[c];
        st[c] = dir ? L : 0;
        if (!dir) {
            const float r0 = __ldg(&em[c][0]) * L2E;
            R[c] = r0;
            V[c][0][lane]      = ex2(fmaf(em[c][lane],      L2E, -r0));
            V[c][0][lane + 32] = ex2(fmaf(em[c][lane + 32], L2E, -r0));
        } else if (ns[c] > 0) {
            const size_t o = (size_t)st[c] * N_;
            const float r0 = __ldg(&em[c][o]) * L2E;
            R[c] = r0;
            V[c][0][lane]      = ex2(fmaf(em[c][o + lane],      L2E, -r0));
            V[c][0][lane + 32] = ex2(fmaf(em[c][o + lane + 32], L2E, -r0));
        } else {
            R[c] = 0.0f;
            V[c][0][lane] = 1.0f;
            V[c][0][lane + 32] = 1.0f;
        }
    }

    float eA[NCH][2], eB[NCH][2];
#pragma unroll
    for (int c = 0; c < NCH; c++) {
        eA[c][0] = eA[c][1] = eB[c][0] = eB[c][1] = 0.f;
        if (1 <= ne[c]) { const int r = (st[c] + dr) * N_;     eA[c][0] = em[c][r + lane]; eA[c][1] = em[c][r + lane + 32]; }
        if (2 <= ne[c]) { const int r = (st[c] + 2 * dr) * N_; eB[c][0] = em[c][r + lane]; eB[c][1] = em[c][r + lane + 32]; }
    }
    __syncwarp();

    int nsMax = ns[0];
#pragma unroll
    for (int c = 1; c < NCH; c++) nsMax = (ns[c] > nsMax) ? ns[c] : nsMax;

    int k = 1;
    for (; k + 1 <= nsMax; k += 2) {
        float nA[NCH][2], nB[NCH][2];
#pragma unroll
        for (int c = 0; c < NCH; c++) {
            nA[c][0] = nA[c][1] = nB[c][0] = nB[c][1] = 0.f;
            if (k + 2 <= ne[c]) { const int r = (st[c] + dr * (k + 2)) * N_; nA[c][0] = em[c][r + lane]; nA[c][1] = em[c][r + lane + 32]; }
            if (k + 3 <= ne[c]) { const int r = (st[c] + dr * (k + 3)) * N_; nB[c][0] = em[c][r + lane]; nB[c][1] = em[c][r + lane + 32]; }
        }
        // ---- step A (rescaled): buf0 -> buf1 ----
        {
            float q[NCH], sLo[NCH], sHi[NCH];
#pragma unroll
            for (int c = 0; c < NCH; c++) q[c] = expq(V[c][0][0]);
#pragma unroll
            for (int c = 0; c < NCH; c++) gemv2(&V[c][0][0], ETlo, EThi, sLo[c], sHi[c]);
#pragma unroll
            for (int c = 0; c < NCH; c++) {
                const float mL = ex2(fmaf(eA[c][0], L2E, -q[c]));
                const float mH = ex2(fmaf(eA[c][1], L2E, -q[c]));
                if (k <= ns[c]) { V[c][1][lane] = mL * sLo[c]; V[c][1][lane + 32] = mH * sHi[c]; R[c] += q[c]; }
            }
            __syncwarp();
        }
        // ---- step B (no rescale): buf1 -> buf0 ----
        {
            float sLo[NCH], sHi[NCH];
#pragma unroll
            for (int c = 0; c < NCH; c++) gemv2(&V[c][1][0], ETlo, EThi, sLo[c], sHi[c]);
#pragma unroll
            for (int c = 0; c < NCH; c++) {
                const float mL = ex2(eB[c][0] * L2E);
                const float mH = ex2(eB[c][1] * L2E);
                if (k + 1 <= ns[c]) { V[c][0][lane] = mL * sLo[c]; V[c][0][lane + 32] = mH * sHi[c]; }
            }
            __syncwarp();
        }
#pragma unroll
        for (int c = 0; c < NCH; c++) {
            eA[c][0] = nA[c][0]; eA[c][1] = nA[c][1];
            eB[c][0] = nB[c][0]; eB[c][1] = nB[c][1];
        }
    }
    if (k <= nsMax) {           // odd leftover A-type step
        float q[NCH], sLo[NCH], sHi[NCH];
#pragma unroll
        for (int c = 0; c < NCH; c++) q[c] = expq(V[c][0][0]);
#pragma unroll
        for (int c = 0; c < NCH; c++) gemv2(&V[c][0][0], ETlo, EThi, sLo[c], sHi[c]);
#pragma unroll
        for (int c = 0; c < NCH; c++) {
            const float mL = ex2(fmaf(eA[c][0], L2E, -q[c]));
            const float mH = ex2(fmaf(eA[c][1], L2E, -q[c]));
            if (k <= ns[c]) { V[c][1][lane] = mL * sLo[c]; V[c][1][lane + 32] = mH * sHi[c]; R[c] += q[c]; }
        }
        __syncwarp();
    }
#pragma unroll
    for (int c = 0; c < NCH; c++) Rout[c] = R[c];
}

__global__ __launch_bounds__(128) void crf_sched(
    const float* __restrict__ inputs,   // [B, T, N]
    const float* __restrict__ trans,    // [N, N]
    const int*   __restrict__ tags,     // [B, T]
    const int*   __restrict__ lens,     // [B]
    float*       __restrict__ out)      // [B + N*N]
{
    const int bid  = blockIdx.x;
    const int tid  = threadIdx.x;
    const int wid  = tid >> 5;
    const int lane = tid & 31;
    const int wg   = bid * 4 + wid;          // global warp slot

    __shared__ __align__(16) float V[4][3][2][68];
    __shared__ float Rsh[4][3];

    // Passthrough copy of transition_params: 128 blocks x 8 float4 = 4096.
    if (bid < 128 && tid < 8) {
        const int idx = bid * 8 + tid;
        reinterpret_cast<float4*>(out + B_)[idx] =
            reinterpret_cast<const float4*>(trans)[idx];
    }

    // Decode my class: nch chains (same direction), batches from sorted order.
    int bb[3] = {0, 0, 0};
    int nch = 0, dir = 0;
    if (wg < W_SOLO) {
        nch = 1; dir = wg & 1;
        bb[0] = d_order[wg >> 1];
    } else if (wg < W_SOLO + W_PAIR) {
        const int i = wg - W_SOLO; dir = i & 1; const int j = i >> 1;
        nch = 2;
        bb[0] = d_order[SOLO_B + 2 * j];
        bb[1] = d_order[SOLO_B + 2 * j + 1];
    } else if (wg < W_SOLO + W_PAIR + W_TRI) {
        const int i = wg - W_SOLO - W_PAIR; dir = i & 1; const int j = i >> 1;
        nch = 3;
        bb[0] = d_order[SOLO_B + 2 * PAIR_B / 2 + 3 * j];       // 260 + 3j
        bb[1] = d_order[SOLO_B + 2 * PAIR_B / 2 + 3 * j + 1];
        bb[2] = d_order[SOLO_B + 2 * PAIR_B / 2 + 3 * j + 2];
    }

    float Rout[3] = {0.f, 0.f, 0.f};
    if (nch > 0) {
        // Register matrix (shared by all my chains; depends only on dir, lane):
        //  fwd: ET*[m] = exp2(trans[2m..][col]*L2E), cols lane, lane+32
        //  bwd: ET*[m] = exp2(trans[col][2m..]*L2E), rows lane, lane+32
        unsigned long long ETlo[32], EThi[32];
#pragma unroll
        for (int m = 0; m < 32; m++) {
            const int iaL = dir ? (lane * N_ + 2 * m)            : ((2 * m) * N_ + lane);
            const int ibL = dir ? (lane * N_ + 2 * m + 1)        : ((2 * m + 1) * N_ + lane);
            const int iaH = dir ? ((lane + 32) * N_ + 2 * m)     : ((2 * m) * N_ + lane + 32);
            const int ibH = dir ? ((lane + 32) * N_ + 2 * m + 1) : ((2 * m + 1) * N_ + lane + 32);
            ETlo[m] = pack2(ex2(trans[iaL] * L2E), ex2(trans[ibL] * L2E));
            EThi[m] = pack2(ex2(trans[iaH] * L2E), ex2(trans[ibH] * L2E));
        }
        if (nch == 1)      run_chains<1>(inputs, lens, bb, dir, lane, ETlo, EThi, V[wid], Rout);
        else if (nch == 2) run_chains<2>(inputs, lens, bb, dir, lane, ETlo, EThi, V[wid], Rout);
        else               run_chains<3>(inputs, lens, bb, dir, lane, ETlo, EThi, V[wid], Rout);
    }

    if (lane == 0) {
        Rsh[wid][0] = Rout[0]; Rsh[wid][1] = Rout[1]; Rsh[wid][2] = Rout[2];
    }
    __syncthreads();

    // Join + output: each FWD warp (even wid pairing; partner = wid+1) handles
    // its nch batches: Z = <v_mid, beta_mid>, plus sequence score.
    if (nch > 0 && dir == 0) {
        for (int c = 0; c < nch; c++) {
            const int b = bb[c];
            const int len = lens[b];
            const int L = (len > 1) ? len - 1 : 0;
            const int fs = L >> 1;
            const int fpar = fs & 1;
            const int bpar = (L - fs) & 1;

            float dv = V[wid][c][fpar][lane]      * V[wid + 1][c][bpar][lane]
                     + V[wid][c][fpar][lane + 32] * V[wid + 1][c][bpar][lane + 32];
#pragma unroll
            for (int off = 16; off; off >>= 1)
                dv += __shfl_xor_sync(0xffffffffu, dv, off);

            const float* emI = inputs + (size_t)b * T_ * N_;
            const int* tgI = tags + b * T_;
            float sc = 0.0f;
            for (int q = lane; q < len; q += 32)
                sc += emI[q * N_ + tgI[q]];
            for (int q = lane + 1; q < len; q += 32)
                sc += trans[tgI[q - 1] * N_ + tgI[q]];
#pragma unroll
            for (int off = 16; off; off >>= 1)
                sc += __shfl_xor_sync(0xffffffffu, sc, off);

            if (lane == 0) {
                const float logZ = (Rout[c] + Rsh[wid + 1][c] + lg2(dv)) * LN2;
                out[b] = sc - logZ;
            }
        }
    }
}

extern "C" void kernel_launch(void* const* d_in, const int* in_sizes, int n_in,
                              void* d_out, int out_size) {
    const float* inputs = (const float*)d_in[0];   // [512, 512, 64] f32
    const float* trans  = (const float*)d_in[1];   // [64, 64] f32
    const int*   tags   = (const int*)d_in[2];     // [512, 512] i32
    const int*   lens   = (const int*)d_in[3];     // [512] i32
    float*       out    = (float*)d_out;           // [512 + 4096] f32

    rank_kernel<<<1, B_>>>(lens);
    crf_sched<<<NBLK, 128>>>(inputs, trans, tags, lens, out);
}

// round 14
// speedup vs baseline: 1.2596x; 1.0589x over previous
#include <cuda_runtime.h>
#include <cuda_bf16.h>

#define B_ 512
#define T_ 512
#define N_ 64

#define L2E 1.4426950408889634f   // log2(e)
#define LN2 0.6931471805599453f   // ln(2)

// Length-scheduled warp classes (batch ranks sorted by len desc), solved from
// the measured cost model c(n) = 256n + 160 cyc/step (FFMA2 rt=4 -> 256 pipe
// cycles per 64x64 GEMV per chain) under the 592-warp single-wave budget:
//  ranks [0,184)   -> SOLO warps (1 chain)  : 368 warps, bound ~106K cyc
//  ranks [184,284) -> PAIR warps (2 chains) : 100 warps, bound ~110K
//  ranks [284,344) -> TRI  warps (3 chains) :  40 warps, bound ~105K
//  ranks [344,512) -> QUAD warps (4 chains) :  84 warps, bound  ~99K
#define R_PAIR 184
#define R_TRI  284
#define R_QUAD 344
#define W_SOLO 368
#define W_PAIR 100
#define W_TRI  40
#define W_QUAD 84
#define NBLK   148        // 148 x 4 = 592 warp slots, exactly 1 per SMSP

__device__ int d_order[B_];

// ---- packed f32x2 + MUFU helpers (sm_103a) ----
__device__ __forceinline__ void ffma2(unsigned long long &d,
                                      unsigned long long a,
                                      unsigned long long b) {
    asm("fma.rn.f32x2 %0, %1, %2, %0;" : "+l"(d) : "l"(a), "l"(b));
}
__device__ __forceinline__ unsigned long long fadd2(unsigned long long a,
                                                    unsigned long long b) {
    unsigned long long d;
    asm("add.rn.f32x2 %0, %1, %2;" : "=l"(d) : "l"(a), "l"(b));
    return d;
}
__device__ __forceinline__ unsigned long long pack2(float lo, float hi) {
    unsigned long long d;
    asm("mov.b64 %0, {%1, %2};" : "=l"(d) : "f"(lo), "f"(hi));
    return d;
}
__device__ __forceinline__ void unpack2(unsigned long long v, float &lo, float &hi) {
    asm("mov.b64 {%0, %1}, %2;" : "=f"(lo), "=f"(hi) : "l"(v));
}
__device__ __forceinline__ float ex2(float x) {
    float r; asm("ex2.approx.f32 %0, %1;" : "=f"(r) : "f"(x)); return r;
}
__device__ __forceinline__ float lg2(float x) {
    float r; asm("lg2.approx.f32 %0, %1;" : "=f"(r) : "f"(x)); return r;
}
// Exact floor-log2 rescale shift via exponent bit-extract (+6 centering).
__device__ __forceinline__ float expq(float E0) {
    return (float)((int)((__float_as_uint(E0) >> 23) & 0xFF) - 121);
}

// Rank batches by length desc (ties by index): d_order[rank] = batch.
__global__ void rank_kernel(const int* __restrict__ lens) {
    __shared__ int sl[B_];
    const int t = threadIdx.x;
    sl[t] = lens[t];
    __syncthreads();
    const int lb = sl[t];
    int r = 0;
#pragma unroll 8
    for (int k = 0; k < B_; k++) {
        const int lk = sl[k];
        r += (lk > lb) || (lk == lb && k < t);
    }
    d_order[r] = t;
}

// Two-column GEMV: 16 broadcast LDS.128 + 64 FFMA2.
__device__ __forceinline__ void gemv2(const float* __restrict__ vsrc,
                                      const unsigned long long* __restrict__ ETlo,
                                      const unsigned long long* __restrict__ EThi,
                                      float &sLo, float &sHi) {
    const ulonglong2* ev = reinterpret_cast<const ulonglong2*>(vsrc);
    unsigned long long l0 = 0ull, l1 = 0ull, l2 = 0ull, l3 = 0ull;
    unsigned long long h0 = 0ull, h1 = 0ull, h2 = 0ull, h3 = 0ull;
#pragma unroll
    for (int m = 0; m < 8; m++) {
        const ulonglong2 p = ev[2 * m];
        const ulonglong2 q = ev[2 * m + 1];
        ffma2(l0, p.x, ETlo[4 * m + 0]);
        ffma2(h0, p.x, EThi[4 * m + 0]);
        ffma2(l1, p.y, ETlo[4 * m + 1]);
        ffma2(h1, p.y, EThi[4 * m + 1]);
        ffma2(l2, q.x, ETlo[4 * m + 2]);
        ffma2(h2, q.x, EThi[4 * m + 2]);
        ffma2(l3, q.y, ETlo[4 * m + 3]);
        ffma2(h3, q.y, EThi[4 * m + 3]);
    }
    float a, b;
    unpack2(fadd2(fadd2(l0, l1), fadd2(l2, l3)), a, b);
    sLo = a + b;
    unpack2(fadd2(fadd2(h0, h1), fadd2(h2, h3)), a, b);
    sHi = a + b;
}

// NCH same-direction chains in one warp (shared register matrix).
// Unroll-2, exact power-of-2 rescale on A-steps (validated r7-r13).
template <int NCH>
__device__ __forceinline__ void run_chains(
    const float* __restrict__ inputs, const int* __restrict__ lens,
    const int* bb, int dir, int lane,
    const unsigned long long* __restrict__ ETlo,
    const unsigned long long* __restrict__ EThi,
    float (*V)[2][68], float* Rout)
{
    const float* em[NCH];
    int ns[NCH], ne[NCH], st[NCH];
    float R[NCH];
    const int dr = dir ? -1 : 1;

#pragma unroll
    for (int c = 0; c < NCH; c++) {
        em[c] = inputs + (size_t)bb[c] * T_ * N_;
        const int len = lens[bb[c]];
        const int L = (len > 1) ? len - 1 : 0;
        const int fs = L >> 1;
        ns[c] = dir ? (L - fs) : fs;
        ne[c] = dir ? (ns[c] - 1) : ns[c];
        st[c] = dir ? L : 0;
        if (!dir) {
            const float r0 = __ldg(&em[c][0]) * L2E;
            R[c] = r0;
            V[c][0][lane]      = ex2(fmaf(em[c][lane],      L2E, -r0));
            V[c][0][lane + 32] = ex2(fmaf(em[c][lane + 32], L2E, -r0));
        } else if (ns[c] > 0) {
            const size_t o = (size_t)st[c] * N_;
            const float r0 = __ldg(&em[c][o]) * L2E;
            R[c] = r0;
            V[c][0][lane]      = ex2(fmaf(em[c][o + lane],      L2E, -r0));
            V[c][0][lane + 32] = ex2(fmaf(em[c][o + lane + 32], L2E, -r0));
        } else {
            R[c] = 0.0f;
            V[c][0][lane] = 1.0f;
            V[c][0][lane + 32] = 1.0f;
        }
    }

    float eA[NCH][2], eB[NCH][2];
#pragma unroll
    for (int c = 0; c < NCH; c++) {
        eA[c][0] = eA[c][1] = eB[c][0] = eB[c][1] = 0.f;
        if (1 <= ne[c]) { const int r = (st[c] + dr) * N_;     eA[c][0] = em[c][r + lane]; eA[c][1] = em[c][r + lane + 32]; }
        if (2 <= ne[c]) { const int r = (st[c] + 2 * dr) * N_; eB[c][0] = em[c][r + lane]; eB[c][1] = em[c][r + lane + 32]; }
    }
    __syncwarp();

    int nsMax = ns[0];
#pragma unroll
    for (int c = 1; c < NCH; c++) nsMax = (ns[c] > nsMax) ? ns[c] : nsMax;

    int k = 1;
    for (; k + 1 <= nsMax; k += 2) {
        float nA[NCH][2], nB[NCH][2];
#pragma unroll
        for (int c = 0; c < NCH; c++) {
            nA[c][0] = nA[c][1] = nB[c][0] = nB[c][1] = 0.f;
            if (k + 2 <= ne[c]) { const int r = (st[c] + dr * (k + 2)) * N_; nA[c][0] = em[c][r + lane]; nA[c][1] = em[c][r + lane + 32]; }
            if (k + 3 <= ne[c]) { const int r = (st[c] + dr * (k + 3)) * N_; nB[c][0] = em[c][r + lane]; nB[c][1] = em[c][r + lane + 32]; }
        }
        // ---- step A (rescaled): buf0 -> buf1 ----
        {
            float q[NCH], sLo[NCH], sHi[NCH];
#pragma unroll
            for (int c = 0; c < NCH; c++) q[c] = expq(V[c][0][0]);
#pragma unroll
            for (int c = 0; c < NCH; c++) gemv2(&V[c][0][0], ETlo, EThi, sLo[c], sHi[c]);
#pragma unroll
            for (int c = 0; c < NCH; c++) {
                const float mL = ex2(fmaf(eA[c][0], L2E, -q[c]));
                const float mH = ex2(fmaf(eA[c][1], L2E, -q[c]));
                if (k <= ns[c]) { V[c][1][lane] = mL * sLo[c]; V[c][1][lane + 32] = mH * sHi[c]; R[c] += q[c]; }
            }
            __syncwarp();
        }
        // ---- step B (no rescale): buf1 -> buf0 ----
        {
            float sLo[NCH], sHi[NCH];
#pragma unroll
            for (int c = 0; c < NCH; c++) gemv2(&V[c][1][0], ETlo, EThi, sLo[c], sHi[c]);
#pragma unroll
            for (int c = 0; c < NCH; c++) {
                const float mL = ex2(eB[c][0] * L2E);
                const float mH = ex2(eB[c][1] * L2E);
                if (k + 1 <= ns[c]) { V[c][0][lane] = mL * sLo[c]; V[c][0][lane + 32] = mH * sHi[c]; }
            }
            __syncwarp();
        }
#pragma unroll
        for (int c = 0; c < NCH; c++) {
            eA[c][0] = nA[c][0]; eA[c][1] = nA[c][1];
            eB[c][0] = nB[c][0]; eB[c][1] = nB[c][1];
        }
    }
    if (k <= nsMax) {           // odd leftover A-type step
        float q[NCH], sLo[NCH], sHi[NCH];
#pragma unroll
        for (int c = 0; c < NCH; c++) q[c] = expq(V[c][0][0]);
#pragma unroll
        for (int c = 0; c < NCH; c++) gemv2(&V[c][0][0], ETlo, EThi, sLo[c], sHi[c]);
#pragma unroll
        for (int c = 0; c < NCH; c++) {
            const float mL = ex2(fmaf(eA[c][0], L2E, -q[c]));
            const float mH = ex2(fmaf(eA[c][1], L2E, -q[c]));
            if (k <= ns[c]) { V[c][1][lane] = mL * sLo[c]; V[c][1][lane + 32] = mH * sHi[c]; R[c] += q[c]; }
        }
        __syncwarp();
    }
#pragma unroll
    for (int c = 0; c < NCH; c++) Rout[c] = R[c];
}

__global__ __launch_bounds__(128) void crf_sched(
    const float* __restrict__ inputs,   // [B, T, N]
    const float* __restrict__ trans,    // [N, N]
    const int*   __restrict__ tags,     // [B, T]
    const int*   __restrict__ lens,     // [B]
    float*       __restrict__ out)      // [B + N*N]
{
    const int bid  = blockIdx.x;
    const int tid  = threadIdx.x;
    const int wid  = tid >> 5;
    const int lane = tid & 31;
    const int wg   = bid * 4 + wid;          // global warp slot

    __shared__ __align__(16) float V[4][4][2][68];
    __shared__ float Rsh[4][4];

    // Passthrough copy of transition_params: 128 blocks x 8 float4 = 4096.
    if (bid < 128 && tid < 8) {
        const int idx = bid * 8 + tid;
        reinterpret_cast<float4*>(out + B_)[idx] =
            reinterpret_cast<const float4*>(trans)[idx];
    }

    // Decode my class: nch same-direction chains, batches from sorted order.
    // Class boundaries are even -> (fwd, bwd) warps are always (even, odd)
    // adjacent slots, i.e. (wid, wid+1) within the block.
    int bb[4] = {0, 0, 0, 0};
    int nch = 0, dir = 0;
    if (wg < W_SOLO) {
        nch = 1; dir = wg & 1;
        bb[0] = d_order[wg >> 1];
    } else if (wg < W_SOLO + W_PAIR) {
        const int i = wg - W_SOLO; dir = i & 1; const int j = i >> 1;
        nch = 2;
        bb[0] = d_order[R_PAIR + 2 * j];
        bb[1] = d_order[R_PAIR + 2 * j + 1];
    } else if (wg < W_SOLO + W_PAIR + W_TRI) {
        const int i = wg - W_SOLO - W_PAIR; dir = i & 1; const int j = i >> 1;
        nch = 3;
        bb[0] = d_order[R_TRI + 3 * j];
        bb[1] = d_order[R_TRI + 3 * j + 1];
        bb[2] = d_order[R_TRI + 3 * j + 2];
    } else {
        const int i = wg - W_SOLO - W_PAIR - W_TRI; dir = i & 1; const int j = i >> 1;
        nch = 4;
        bb[0] = d_order[R_QUAD + 4 * j];
        bb[1] = d_order[R_QUAD + 4 * j + 1];
        bb[2] = d_order[R_QUAD + 4 * j + 2];
        bb[3] = d_order[R_QUAD + 4 * j + 3];
    }

    float Rout[4] = {0.f, 0.f, 0.f, 0.f};
    {
        // Register matrix (shared by all my chains; depends only on dir, lane):
        //  fwd: ET*[m] = exp2(trans[2m..][col]*L2E), cols lane, lane+32
        //  bwd: ET*[m] = exp2(trans[col][2m..]*L2E), rows lane, lane+32
        unsigned long long ETlo[32], EThi[32];
#pragma unroll
        for (int m = 0; m < 32; m++) {
            const int iaL = dir ? (lane * N_ + 2 * m)            : ((2 * m) * N_ + lane);
            const int ibL = dir ? (lane * N_ + 2 * m + 1)        : ((2 * m + 1) * N_ + lane);
            const int iaH = dir ? ((lane + 32) * N_ + 2 * m)     : ((2 * m) * N_ + lane + 32);
            const int ibH = dir ? ((lane + 32) * N_ + 2 * m + 1) : ((2 * m + 1) * N_ + lane + 32);
            ETlo[m] = pack2(ex2(trans[iaL] * L2E), ex2(trans[ibL] * L2E));
            EThi[m] = pack2(ex2(trans[iaH] * L2E), ex2(trans[ibH] * L2E));
        }
        if (nch == 1)      run_chains<1>(inputs, lens, bb, dir, lane, ETlo, EThi, V[wid], Rout);
        else if (nch == 2) run_chains<2>(inputs, lens, bb, dir, lane, ETlo, EThi, V[wid], Rout);
        else if (nch == 3) run_chains<3>(inputs, lens, bb, dir, lane, ETlo, EThi, V[wid], Rout);
        else               run_chains<4>(inputs, lens, bb, dir, lane, ETlo, EThi, V[wid], Rout);
    }

    if (lane == 0) {
        Rsh[wid][0] = Rout[0]; Rsh[wid][1] = Rout[1];
        Rsh[wid][2] = Rout[2]; Rsh[wid][3] = Rout[3];
    }
    __syncthreads();

    // Join + output: each FWD warp (even wid; partner = wid+1) handles its
    // nch batches: Z = <v_mid, beta_mid>, plus sequence score.
    if (dir == 0) {
        for (int c = 0; c < nch; c++) {
            const int b = bb[c];
            const int len = lens[b];
            const int L = (len > 1) ? len - 1 : 0;
            const int fs = L >> 1;
            const int fpar = fs & 1;
            const int bpar = (L - fs) & 1;

            float dv = V[wid][c][fpar][lane]      * V[wid + 1][c][bpar][lane]
                     + V[wid][c][fpar][lane + 32] * V[wid + 1][c][bpar][lane + 32];
#pragma unroll
            for (int off = 16; off; off >>= 1)
                dv += __shfl_xor_sync(0xffffffffu, dv, off);

            const float* emI = inputs + (size_t)b * T_ * N_;
            const int* tgI = tags + b * T_;
            float sc = 0.0f;
            for (int q = lane; q < len; q += 32)
                sc += emI[q * N_ + tgI[q]];
            for (int q = lane + 1; q < len; q += 32)
                sc += trans[tgI[q - 1] * N_ + tgI[q]];
#pragma unroll
            for (int off = 16; off; off >>= 1)
                sc += __shfl_xor_sync(0xffffffffu, sc, off);

            if (lane == 0) {
                const float logZ = (Rout[c] + Rsh[wid + 1][c] + lg2(dv)) * LN2;
                out[b] = sc - logZ;
            }
        }
    }
}

extern "C" void kernel_launch(void* const* d_in, const int* in_sizes, int n_in,
                              void* d_out, int out_size) {
    const float* inputs = (const float*)d_in[0];   // [512, 512, 64] f32
    const float* trans  = (const float*)d_in[1];   // [64, 64] f32
    const int*   tags   = (const int*)d_in[2];     // [512, 512] i32
    const int*   lens   = (const int*)d_in[3];     // [512] i32
    float*       out    = (float*)d_out;           // [512 + 4096] f32

    rank_kernel<<<1, B_>>>(lens);
    crf_sched<<<NBLK, 128>>>(inputs, trans, tags, lens, out);
}